// round 1
// baseline (speedup 1.0000x reference)
#include <cuda_runtime.h>

// CostVolume: B=4, C=128, H=128, W=256, r=4, D=81
// out[b,k,h,w] = (1/81) * sum_c x1[b,c,h,w] * x2[b,c,h-i,w-j],  k=(9i+j) mod 81
//
// Block (8,4,9): tx = w-oct (8 pixels each, TW=64), ty = h row (TH=4),
// tz = row-shift group i = tz-4. Each thread accumulates 9 (j-shifts) x 8 (pixels)
// outputs as 36 f32x2 pairs, using packed fma.rn.f32x2 (sm_100+).

#define C_DIM 128
#define H_DIM 128
#define W_DIM 256
#define D_DIM 81

#define TH 4
#define TW 64
#define TWR 8
#define CC 4            // channels per chunk
#define NCHUNK (C_DIM / CC)   // 32
#define TH8 (TH + 8)    // 12
#define TW8 (TW + 8)    // 72
#define THREADS 288     // 8 * 4 * 9

#define S2_ELEMS (CC * TH8 * TW8)   // 3456
#define S1_ELEMS (CC * TH * TW)     // 1024
#define S_TOTAL  (S2_ELEMS + S1_ELEMS)  // 4480
#define PF_N 16         // ceil(4480 / 288)

__device__ __forceinline__ void ffma2(float2& d, const float2 a, const float2 b) {
    asm("{\n\t"
        ".reg .b64 ra, rb, rd;\n\t"
        "mov.b64 ra, {%2, %3};\n\t"
        "mov.b64 rb, {%4, %5};\n\t"
        "mov.b64 rd, {%0, %1};\n\t"
        "fma.rn.f32x2 rd, ra, rb, rd;\n\t"
        "mov.b64 {%0, %1}, rd;\n\t"
        "}"
        : "+f"(d.x), "+f"(d.y)
        : "f"(a.x), "f"(a.y), "f"(b.x), "f"(b.y));
}

__global__ __launch_bounds__(THREADS) void cost_volume_kernel(
    const float* __restrict__ x1,
    const float* __restrict__ x2,
    float* __restrict__ out)
{
    __shared__ float smem[S_TOTAL];   // [0, S2_ELEMS): x2 tile, then x1 tile

    const int tx = threadIdx.x;           // 0..7  (w oct)
    const int ty = threadIdx.y;           // 0..3  (h row)
    const int tz = threadIdx.z;           // 0..8  (i group)
    const int tid = tx + 8 * ty + 32 * tz;

    const int w0 = blockIdx.x * TW;
    const int h0 = blockIdx.y * TH;
    const int b  = blockIdx.z;

    const int h  = h0 + ty;
    const int wb = w0 + tx * TWR;
    const int r2 = ty + 8 - tz;           // row in x2 tile for this thread's i

    // ---- accumulators: 9 jj x 4 pixel-pairs ----
    float2 acc[9][4];
#pragma unroll
    for (int jj = 0; jj < 9; jj++)
#pragma unroll
        for (int tp = 0; tp < 4; tp++)
            acc[jj][tp] = make_float2(0.f, 0.f);

    // ---- staging helpers (register prefetch of one CC-channel chunk) ----
    float pf[PF_N];

    auto stage_load = [&](int c0) {
#pragma unroll
        for (int u = 0; u < PF_N; u++) {
            const int idx = tid + u * THREADS;
            if (idx < S2_ELEMS) {
                const int c   = idx / (TH8 * TW8);
                const int rem = idx - c * (TH8 * TW8);
                const int row = rem / TW8;
                const int col = rem - row * TW8;
                const int gh = h0 - 4 + row;
                const int gw = w0 - 4 + col;
                float v = 0.f;
                if ((unsigned)gh < (unsigned)H_DIM && (unsigned)gw < (unsigned)W_DIM)
                    v = x2[(((long)b * C_DIM + (c0 + c)) * H_DIM + gh) * W_DIM + gw];
                pf[u] = v;
            } else if (idx < S_TOTAL) {
                const int idx2 = idx - S2_ELEMS;
                const int c   = idx2 >> 8;        // / 256
                const int rem = idx2 & 255;
                const int row = rem >> 6;         // / 64
                const int col = rem & 63;
                pf[u] = x1[(((long)b * C_DIM + (c0 + c)) * H_DIM + (h0 + row)) * W_DIM + (w0 + col)];
            }
        }
    };

    auto stage_store = [&]() {
#pragma unroll
        for (int u = 0; u < PF_N; u++) {
            const int idx = tid + u * THREADS;
            if (idx < S_TOTAL) smem[idx] = pf[u];
        }
    };

    // ---- main loop over channel chunks ----
    stage_load(0);

    for (int ch = 0; ch < NCHUNK; ch++) {
        __syncthreads();      // previous chunk's compute done
        stage_store();
        __syncthreads();      // tile visible
        if (ch + 1 < NCHUNK) stage_load((ch + 1) * CC);   // overlap LDG with compute

#pragma unroll
        for (int c = 0; c < CC; c++) {
            // x1: 8 pixels -> 4 aligned float2
            const float2* ap =
                (const float2*)&smem[S2_ELEMS + (c * TH + ty) * TW + tx * TWR];
            float2 a0 = ap[0], a1 = ap[1], a2 = ap[2], a3 = ap[3];

            // x2 window: 16 floats as 8 aligned float2 (even pairs)
            const float2* wp = (const float2*)&smem[(c * TH8 + r2) * TW8 + tx * TWR];
            float2 we[8];
#pragma unroll
            for (int q = 0; q < 8; q++) we[q] = wp[q];

#pragma unroll
            for (int jj = 0; jj < 9; jj++) {
                const int qb = jj >> 1;
                if ((jj & 1) == 0) {
                    ffma2(acc[jj][0], a0, we[qb + 0]);
                    ffma2(acc[jj][1], a1, we[qb + 1]);
                    ffma2(acc[jj][2], a2, we[qb + 2]);
                    ffma2(acc[jj][3], a3, we[qb + 3]);
                } else {
                    // odd pairs (win[2q+1], win[2q+2])
                    float2 b0 = make_float2(we[qb + 0].y, we[qb + 1].x);
                    float2 b1 = make_float2(we[qb + 1].y, we[qb + 2].x);
                    float2 b2 = make_float2(we[qb + 2].y, we[qb + 3].x);
                    float2 b3 = make_float2(we[qb + 3].y, we[qb + 4].x);
                    ffma2(acc[jj][0], a0, b0);
                    ffma2(acc[jj][1], a1, b1);
                    ffma2(acc[jj][2], a2, b2);
                    ffma2(acc[jj][3], a3, b3);
                }
            }
        }
    }

    // ---- epilogue ----
    const float invD = (float)(1.0 / 81.0);
    const int i_d = tz - 4;
#pragma unroll
    for (int jj = 0; jj < 9; jj++) {
        const int j_d = 4 - jj;
        int k = 9 * i_d + j_d;
        k %= D_DIM;
        if (k < 0) k += D_DIM;

        float* op = out + ((((long)b * D_DIM + k) * H_DIM + h) * W_DIM + wb);
        float4 v0 = make_float4(acc[jj][0].x * invD, acc[jj][0].y * invD,
                                acc[jj][1].x * invD, acc[jj][1].y * invD);
        float4 v1 = make_float4(acc[jj][2].x * invD, acc[jj][2].y * invD,
                                acc[jj][3].x * invD, acc[jj][3].y * invD);
        ((float4*)op)[0] = v0;
        ((float4*)op)[1] = v1;
    }
}

extern "C" void kernel_launch(void* const* d_in, const int* in_sizes, int n_in,
                              void* d_out, int out_size)
{
    const float* x1 = (const float*)d_in[0];
    const float* x2 = (const float*)d_in[1];
    float* out = (float*)d_out;

    dim3 block(8, TH, 9);                       // 288 threads
    dim3 grid(W_DIM / TW, H_DIM / TH, 4);       // (4, 32, 4) = 512 blocks
    cost_volume_kernel<<<grid, block>>>(x1, x2, out);
}

// round 3
// speedup vs baseline: 1.8467x; 1.8467x over previous
#include <cuda_runtime.h>
#include <cstdint>

// CostVolume: B=4, C=128, H=128, W=256, r=4, D=81
// out[b,k,h,w] = (1/81) * sum_c x1[b,c,h,w] * x2[b,c,h-i,w-j],  k=(9i+j) mod 81
//
// Block (8,4,9): tx = w-oct (8 px), ty = h row (TH=4), tz = row-shift i = tz-4.
// Per-thread: 9 j-shifts x 8 px = 36 f32x2 accumulators (fma.rn.f32x2).
// cp.async double-buffered smem staging, one __syncthreads per channel chunk.

#define C_DIM 128
#define H_DIM 128
#define W_DIM 256
#define D_DIM 81

#define TH 4
#define TW 64
#define TH8 12            // TH + 8
#define TW8 72            // TW + 8
#define CC 4              // channels per chunk
#define NCHUNK 32         // C / CC
#define THREADS 288       // 8*4*9

#define S2_ELEMS (CC * TH8 * TW8)     // 3456 floats (x2 tile)
#define S1_ELEMS (CC * TH * TW)       // 1024 floats (x1 tile)
#define SST (S2_ELEMS + S1_ELEMS)     // 4480 floats per stage
#define CHUNK_STRIDE (CC * H_DIM * W_DIM)   // 131072 floats

__device__ __forceinline__ void ffma2(float2& d, float ax, float ay, float bx, float by) {
    asm("{\n\t"
        ".reg .b64 ra, rb, rd;\n\t"
        "mov.b64 ra, {%2, %3};\n\t"
        "mov.b64 rb, {%4, %5};\n\t"
        "mov.b64 rd, {%0, %1};\n\t"
        "fma.rn.f32x2 rd, ra, rb, rd;\n\t"
        "mov.b64 {%0, %1}, rd;\n\t"
        "}"
        : "+f"(d.x), "+f"(d.y)
        : "f"(ax), "f"(ay), "f"(bx), "f"(by));
}

__global__ __launch_bounds__(THREADS, 2) void cost_volume_kernel(
    const float* __restrict__ x1,
    const float* __restrict__ x2,
    float* __restrict__ out)
{
    __shared__ float smem[2 * SST];   // 35.8 KB, double-buffered

    const int tx = threadIdx.x;           // 0..7
    const int ty = threadIdx.y;           // 0..3
    const int tz = threadIdx.z;           // 0..8
    const int tid = tx + 8 * ty + 32 * tz;

    const int w0 = blockIdx.x * TW;
    const int h0 = blockIdx.y * TH;
    const int b  = blockIdx.z;

    const int h  = h0 + ty;
    const int wb = w0 + tx * 8;
    const int r2 = ty + 8 - tz;           // row in x2 tile for this thread's i

    const uint32_t smem_base = (uint32_t)__cvta_generic_to_shared(smem);

    // ---- one-time staging address setup ------------------------------------
    // 1120 16B-granules per stage: granules 0..863 = x2 (exactly 3*288),
    // granules 864..1119 = x1 (tid < 256).
    const float* gp[3];
    uint32_t so[3];
    uint32_t ss[3];
#pragma unroll
    for (int u = 0; u < 3; u++) {
        const int gi   = tid + u * THREADS;           // 0..863
        const int row  = gi / 18;
        const int col4 = (gi - row * 18) * 4;
        const int c    = row / TH8;
        const int r    = row - c * TH8;
        so[u] = (uint32_t)(((c * TH8 + r) * TW8 + col4) * 4);
        const int gh = h0 - 4 + r;
        const int gw = w0 - 4 + col4;
        const bool v = (gh >= 0) && (gh < H_DIM) && (gw >= 0) && (gw <= W_DIM - 4);
        ss[u] = v ? 16u : 0u;
        gp[u] = x2 + (v ? ((((long)b * C_DIM + c) * H_DIM + gh) * W_DIM + gw) : 0);
    }
    const bool hasx1 = (tid < 256);
    const int  xrow  = tid >> 4;                      // 0..15
    const int  xcol4 = (tid & 15) * 4;
    const int  xc    = xrow >> 2;
    const int  xhr   = xrow & 3;
    const uint32_t sox = (uint32_t)((S2_ELEMS + (xc * TH + xhr) * TW + xcol4) * 4);
    const float* gpx = x1 + ((((long)b * C_DIM + xc) * H_DIM + (h0 + xhr)) * W_DIM + (w0 + xcol4));

    // ---- accumulators ------------------------------------------------------
    float2 acc[9][4];
#pragma unroll
    for (int jj = 0; jj < 9; jj++)
#pragma unroll
        for (int t = 0; t < 4; t++)
            acc[jj][t] = make_float2(0.f, 0.f);

    // ---- prologue: stage chunk 0 -------------------------------------------
    {
        const uint32_t sb = smem_base;
#pragma unroll
        for (int u = 0; u < 3; u++)
            asm volatile("cp.async.cg.shared.global [%0], [%1], 16, %2;\n"
                         :: "r"(sb + so[u]), "l"(gp[u]), "r"(ss[u]));
        if (hasx1)
            asm volatile("cp.async.cg.shared.global [%0], [%1], 16;\n"
                         :: "r"(sb + sox), "l"(gpx));
        asm volatile("cp.async.commit_group;" ::: "memory");
        gp[0] += CHUNK_STRIDE; gp[1] += CHUNK_STRIDE; gp[2] += CHUNK_STRIDE;
        gpx += CHUNK_STRIDE;
    }

    // ---- main loop ---------------------------------------------------------
    for (int ch = 0; ch < NCHUNK; ch++) {
        asm volatile("cp.async.wait_group 0;" ::: "memory");
        __syncthreads();

        if (ch + 1 < NCHUNK) {
            const uint32_t sb = smem_base + ((ch + 1) & 1) * (SST * 4);
#pragma unroll
            for (int u = 0; u < 3; u++)
                asm volatile("cp.async.cg.shared.global [%0], [%1], 16, %2;\n"
                             :: "r"(sb + so[u]), "l"(gp[u]), "r"(ss[u]));
            if (hasx1)
                asm volatile("cp.async.cg.shared.global [%0], [%1], 16;\n"
                             :: "r"(sb + sox), "l"(gpx));
            asm volatile("cp.async.commit_group;" ::: "memory");
            gp[0] += CHUNK_STRIDE; gp[1] += CHUNK_STRIDE; gp[2] += CHUNK_STRIDE;
            gpx += CHUNK_STRIDE;
        }

        const float* sm = smem + (ch & 1) * SST;
#pragma unroll
        for (int c = 0; c < CC; c++) {
            const float* s1r = sm + S2_ELEMS + (c * TH + ty) * TW + tx * 8;
            const float4 A0 = *(const float4*)s1r;
            const float4 A1 = *(const float4*)(s1r + 4);
            const float a[8] = {A0.x, A0.y, A0.z, A0.w, A1.x, A1.y, A1.z, A1.w};

            const float* wr = sm + (c * TH8 + r2) * TW8 + tx * 8;
            float w[16];
            *(float4*)(w + 0)  = *(const float4*)(wr + 0);
            *(float4*)(w + 4)  = *(const float4*)(wr + 4);
            *(float4*)(w + 8)  = *(const float4*)(wr + 8);
            *(float4*)(w + 12) = *(const float4*)(wr + 12);

#pragma unroll
            for (int jj = 0; jj < 9; jj++)
#pragma unroll
                for (int t = 0; t < 4; t++)
                    ffma2(acc[jj][t], a[2 * t], a[2 * t + 1],
                          w[jj + 2 * t], w[jj + 2 * t + 1]);
        }
    }

    // ---- epilogue ----------------------------------------------------------
    const float invD = (float)(1.0 / 81.0);
    const int i_d = tz - 4;
#pragma unroll
    for (int jj = 0; jj < 9; jj++) {
        const int j_d = 4 - jj;
        int k = 9 * i_d + j_d;
        k %= D_DIM;
        if (k < 0) k += D_DIM;

        float* op = out + ((((long)b * D_DIM + k) * H_DIM + h) * W_DIM + wb);
        const float4 v0 = make_float4(acc[jj][0].x * invD, acc[jj][0].y * invD,
                                      acc[jj][1].x * invD, acc[jj][1].y * invD);
        const float4 v1 = make_float4(acc[jj][2].x * invD, acc[jj][2].y * invD,
                                      acc[jj][3].x * invD, acc[jj][3].y * invD);
        ((float4*)op)[0] = v0;
        ((float4*)op)[1] = v1;
    }
}

extern "C" void kernel_launch(void* const* d_in, const int* in_sizes, int n_in,
                              void* d_out, int out_size)
{
    const float* x1 = (const float*)d_in[0];
    const float* x2 = (const float*)d_in[1];
    float* out = (float*)d_out;

    dim3 block(8, TH, 9);                       // 288 threads
    dim3 grid(W_DIM / TW, H_DIM / TH, 4);       // (4, 32, 4) = 512 blocks
    cost_volume_kernel<<<grid, block>>>(x1, x2, out);
}